// round 5
// baseline (speedup 1.0000x reference)
#include <cuda_runtime.h>
#include <cuda_bf16.h>
#include <math.h>

// ---------------- problem constants ----------------
#define BATCH 256
#define CIN   22
#define WIN   9
#define SEG   125
#define OUTC  64
#define KS    63
#define NCLS  4
#define TLEN  1125          // WIN*SEG
#define NEDGE 231           // 22*21/2

typedef unsigned long long ull;

// ---------------- device scratch (no runtime alloc allowed) ----------------
__device__ float g_W1[OUTC * CIN];          // folded spatial conv (sg * sconv @ As2)
__device__ float g_sb[OUTC];                // folded sbn bias
__device__ float g_tg[OUTC];                // tbn scale
__device__ float g_tb[OUTC];                // tbn bias
__device__ float g_Atb2[WIN * WIN];         // A_tb^2
__device__ float g_fcA[NCLS * OUTC * WIN];  // fc_a folded with A_ta^2
__device__ float g_xb[BATCH * CIN * TLEN];  // time-mixed input (branch B)
__device__ float g_w2[CIN * KS * OUTC];     // folded conv weights [c][k][o]
__device__ float g_C[OUTC * (KS + 1)];      // bias cumsum: C[o][kk] = sum_{k<kk} q[o][k]
__device__ float g_pool[2 * BATCH * OUTC * WIN];// seg-pooled conv output
__device__ float g_xmean[BATCH * CIN];      // mean over T of x

// ---------------- f32x2 helpers ----------------
__device__ __forceinline__ void fma2(ull& d, ull a, ull b) {
    asm("fma.rn.f32x2 %0, %1, %2, %0;" : "+l"(d) : "l"(a), "l"(b));
}
__device__ __forceinline__ ull dup2(float x) {
    ull r; asm("mov.b64 %0, {%1, %1};" : "=l"(r) : "f"(x)); return r;
}
__device__ __forceinline__ void unpack2(ull v, float& lo, float& hi) {
    asm("mov.b64 {%0, %1}, %2;" : "=f"(lo), "=f"(hi) : "l"(v));
}
__device__ __forceinline__ float gelu_exact(float x) {
    return 0.5f * x * (1.f + erff(x * 0.70710678118654752440f));
}

// ============================================================
// Kernel 0: all small precompute (1 block, 256 threads)
// ============================================================
__global__ void k_prep(const float* __restrict__ ew,
                       const float* __restrict__ sconv_w,
                       const float* __restrict__ sbn_g, const float* __restrict__ sbn_b,
                       const float* __restrict__ sbn_m, const float* __restrict__ sbn_v,
                       const float* __restrict__ tbn_g, const float* __restrict__ tbn_b,
                       const float* __restrict__ tbn_m, const float* __restrict__ tbn_v,
                       const float* __restrict__ adj_after,
                       const float* __restrict__ adj_before,
                       const float* __restrict__ fc_a_w,
                       float* __restrict__ out)
{
    __shared__ float A[484], As[484], As2[484], d22[22];
    __shared__ float Mt[81], At[81], At2[81], d9[9];
    const int tid = threadIdx.x;

    // ---- spatial adjacency ----
    for (int idx = tid; idx < 484; idx += 256) {
        int i = idx / 22, j = idx - i * 22;
        A[idx] = (i == j) ? 1.f : 0.f;
    }
    __syncthreads();
    if (tid < NEDGE) {
        int e = tid, i = 1, base = 0;
        while (e >= base + i) { base += i; i++; }
        int j = e - base;
        float v = ew[tid];
        A[i * 22 + j] = v; A[j * 22 + i] = v;
    }
    __syncthreads();
    if (tid < 22) {
        float s = 0.f;
        for (int j = 0; j < 22; j++) s += A[tid * 22 + j];
        d22[tid] = rsqrtf(s);
    }
    __syncthreads();
    for (int idx = tid; idx < 484; idx += 256) {
        int i = idx / 22, j = idx - i * 22;
        As[idx] = A[idx] * d22[i] * d22[j];
    }
    __syncthreads();
    for (int idx = tid; idx < 484; idx += 256) {
        out[1024 + idx] = As[idx];
        out[1670 + idx] = As[idx];
        int i = idx / 22, j = idx - i * 22;
        float s = 0.f;
        for (int k = 0; k < 22; k++) s += As[i * 22 + k] * As[k * 22 + j];
        As2[idx] = s;
    }
    __syncthreads();

    // ---- fold spatial conv + sbn: W1[o][c] = sg[o]*sum_c2 sconv[o][c2]*As2[c2][c] ----
    for (int idx = tid; idx < OUTC * CIN; idx += 256) {
        int o = idx / CIN, c = idx - o * CIN;
        float s = 0.f;
        for (int c2 = 0; c2 < CIN; c2++) s += sconv_w[o * CIN + c2] * As2[c2 * 22 + c];
        float sg = sbn_g[o] * rsqrtf(sbn_v[o] + 1e-5f);
        g_W1[idx] = sg * s;
    }
    if (tid < OUTC) {
        float sg = sbn_g[tid] * rsqrtf(sbn_v[tid] + 1e-5f);
        g_sb[tid] = sbn_b[tid] - sbn_m[tid] * sg;
        float tg = tbn_g[tid] * rsqrtf(tbn_v[tid] + 1e-5f);
        g_tg[tid] = tg;
        g_tb[tid] = tbn_b[tid] - tbn_m[tid] * tg;
    }

    // ---- A_ta (after) ----
    if (tid < 81) {
        int i = tid / 9, j = tid - i * 9;
        Mt[tid] = 0.5f * (adj_after[i * 9 + j] + adj_after[j * 9 + i]);
    }
    __syncthreads();
    if (tid < 9) {
        float s = 0.f;
        for (int j = 0; j < 9; j++) s += Mt[tid * 9 + j];
        d9[tid] = rsqrtf(s);
    }
    __syncthreads();
    if (tid < 81) {
        int i = tid / 9, j = tid - i * 9;
        At[tid] = Mt[tid] * d9[i] * d9[j];
        out[1508 + tid] = At[tid];
    }
    __syncthreads();
    if (tid < 81) {
        int i = tid / 9, j = tid - i * 9;
        float s = 0.f;
        for (int k = 0; k < 9; k++) s += At[i * 9 + k] * At[k * 9 + j];
        At2[tid] = s;
    }
    __syncthreads();
    // fold fc_a with A_ta^2: fcA[n][o][w] = sum_wp fc_a_w[n][o*9+wp] * At2[wp][w]
    for (int idx = tid; idx < NCLS * OUTC * WIN; idx += 256) {
        int n = idx / (OUTC * WIN);
        int rem = idx - n * OUTC * WIN;
        int o = rem / WIN, w = rem - o * WIN;
        float s = 0.f;
        for (int wp = 0; wp < 9; wp++) s += fc_a_w[n * 576 + o * 9 + wp] * At2[wp * 9 + w];
        g_fcA[idx] = s;
    }
    __syncthreads();

    // ---- A_tb (before) ----
    if (tid < 81) {
        int i = tid / 9, j = tid - i * 9;
        Mt[tid] = 0.5f * (adj_before[i * 9 + j] + adj_before[j * 9 + i]);
    }
    __syncthreads();
    if (tid < 9) {
        float s = 0.f;
        for (int j = 0; j < 9; j++) s += Mt[tid * 9 + j];
        d9[tid] = rsqrtf(s);
    }
    __syncthreads();
    if (tid < 81) {
        int i = tid / 9, j = tid - i * 9;
        At[tid] = Mt[tid] * d9[i] * d9[j];
        out[1589 + tid] = At[tid];
    }
    __syncthreads();
    if (tid < 81) {
        int i = tid / 9, j = tid - i * 9;
        float s = 0.f;
        for (int k = 0; k < 9; k++) s += At[i * 9 + k] * At[k * 9 + j];
        g_Atb2[tid] = s;
    }
}

// ============================================================
// Kernel: fold W1 into tconv -> g_w2[c][k][o] = sum_i w[o][i][k] * W1[i][c]
// ============================================================
__global__ void k_wt2(const float* __restrict__ tconv_w) {
    int idx = blockIdx.x * 256 + threadIdx.x;
    if (idx < CIN * KS * OUTC) {
        int c = idx / (KS * OUTC);
        int r = idx - c * (KS * OUTC);
        int k = r / OUTC, o = r - k * OUTC;
        float s = 0.f;
        #pragma unroll 8
        for (int i = 0; i < OUTC; i++)
            s += tconv_w[(o * OUTC + i) * KS + k] * g_W1[i * CIN + c];
        g_w2[idx] = s;
    }
}

// ============================================================
// Kernel: bias cumsum C[o][kk] = sum_{k<kk} sum_i w[o][i][k]*sb[i]
// ============================================================
__global__ void k_bias(const float* __restrict__ tconv_w) {
    int o = threadIdx.x;
    if (o >= OUTC) return;
    float cum = 0.f;
    g_C[o * (KS + 1)] = 0.f;
    for (int k = 0; k < KS; k++) {
        float q = 0.f;
        for (int i = 0; i < OUTC; i++)
            q += tconv_w[(o * OUTC + i) * KS + k] * g_sb[i];
        cum += q;
        g_C[o * (KS + 1) + k + 1] = cum;
    }
}

// ============================================================
// Kernel: branch-B time mix with the reference's VIEW REGROUPING.
//   xb[b, r, p*SEG+s] = sum_p' Atb2[p,p'] * x[b, c', w'*SEG+s], m'=22p'+r
// one block per (b, r), thread = s
// ============================================================
__global__ void k_xb(const float* __restrict__ x) {
    const int bk = blockIdx.x;              // b*22 + r
    const int b = bk / CIN, r = bk - b * CIN;
    const int s = threadIdx.x;
    if (s >= SEG) return;
    float v[WIN];
    #pragma unroll
    for (int pp = 0; pp < WIN; pp++) {
        int m = 22 * pp + r;
        int c = m / 9, w = m - c * 9;
        v[pp] = x[((size_t)b * CIN + c) * TLEN + w * SEG + s];
    }
    float* dst = g_xb + ((size_t)b * CIN + r) * TLEN + s;
    #pragma unroll
    for (int p = 0; p < WIN; p++) {
        float a = 0.f;
        #pragma unroll
        for (int pp = 0; pp < WIN; pp++)
            a = fmaf(g_Atb2[p * 9 + pp], v[pp], a);
        dst[p * SEG] = a;
    }
}

// ============================================================
// Kernel: temporal mean of x per (b,c) for branch C
// ============================================================
__global__ void k_mean(const float* __restrict__ x) {
    __shared__ float red[4];
    const int rc = blockIdx.x;              // b*CIN + c
    const float* src = x + (size_t)rc * TLEN;
    float psum = 0.f;
    for (int idx = threadIdx.x; idx < TLEN; idx += 128) psum += src[idx];
    for (int m = 16; m >= 1; m >>= 1) psum += __shfl_xor_sync(0xffffffffu, psum, m);
    if ((threadIdx.x & 31) == 0) red[threadIdx.x >> 5] = psum;
    __syncthreads();
    if (threadIdx.x == 0)
        g_xmean[rc] = (red[0] + red[1] + red[2] + red[3]) * (1.f / (float)TLEN);
}

// ============================================================
// MAIN kernel: folded conv (22 in ch, K=63) + bias + tbn + GELU + seg-mean pool
// grid: (WIN=9, 512 = br*256+b), 256 threads, dynamic smem
// thread tile: 8 t (tx of 16) x 4 o (ty of 16); f32x2 packs o-pairs
// ============================================================
#define YSTRIDE 192
#define WSZ (KS * OUTC)     // 4032
#define K3_SMEM ((CIN * YSTRIDE + 2 * WSZ + OUTC * (KS + 1)) * 4)  // (4224+8064+4096)*4 = 65536

__global__ void __launch_bounds__(256, 2) k_conv2(const float* __restrict__ x) {
    extern __shared__ float sm[];
    float* y_s = sm;                          // [22][192]
    float* w_s = sm + CIN * YSTRIDE;          // [2][63*64]
    float* c_s = w_s + 2 * WSZ;               // [64][64]
    const int w = blockIdx.x;                 // window
    const int bb = blockIdx.y;                // br*256 + b
    const int br = bb >> 8, b = bb & 255;
    const int tid = threadIdx.x;
    const int tx = tid & 15;
    const int ty = tid >> 4;
    const int o0 = ty * 4;
    const int t0 = w * SEG - 31;
    const float* src = (br ? g_xb : x) + (size_t)b * CIN * TLEN;

    // load input halo tile (187 valid positions per channel, zero-padded)
    for (int idx = tid; idx < CIN * YSTRIDE; idx += 256) {
        int c = idx / YSTRIDE, tt = idx - c * YSTRIDE;
        int gt = t0 + tt;
        float v = (gt >= 0 && gt < TLEN && tt < 187) ? src[(size_t)c * TLEN + gt] : 0.f;
        y_s[c * YSTRIDE + tt] = v;
    }
    // bias cumsum table
    for (int idx = tid; idx < OUTC * (KS + 1); idx += 256) c_s[idx] = g_C[idx];
    // first weight slab
    for (int idx = tid; idx < WSZ; idx += 256) w_s[idx] = g_w2[idx];
    __syncthreads();

    ull acc0[8], acc1[8];
    #pragma unroll
    for (int r = 0; r < 8; r++) { acc0[r] = 0ull; acc1[r] = 0ull; }

    for (int i = 0; i < CIN; ++i) {
        // prefetch next channel's weights into registers (hidden under compute)
        float pf[16];
        if (i < CIN - 1) {
            const float* wg = g_w2 + (i + 1) * WSZ;
            #pragma unroll
            for (int j = 0; j < 15; j++) pf[j] = wg[j * 256 + tid];
            pf[15] = (15 * 256 + tid < WSZ) ? wg[15 * 256 + tid] : 0.f;
        }

        const float* wc = w_s + (i & 1) * WSZ;
        const float* yr = y_s + i * YSTRIDE + tx * 8;
        ull yw[8];
        #pragma unroll
        for (int r = 0; r < 8; r++) yw[r] = dup2(yr[r]);

        #pragma unroll
        for (int k = 0; k < KS; k++) {
            ull wa = *(const ull*)(wc + k * OUTC + o0);
            ull wb = *(const ull*)(wc + k * OUTC + o0 + 2);
            #pragma unroll
            for (int r = 0; r < 8; r++) {
                ull yv = yw[(k + r) & 7];
                fma2(acc0[r], wa, yv);
                fma2(acc1[r], wb, yv);
            }
            if (k < KS - 1) yw[k & 7] = dup2(yr[k + 8]);
        }

        __syncthreads();   // all threads done reading w_s[(i)&1] from this iter (and [(i+1)&1] from prev)
        if (i < CIN - 1) {
            float* wn = w_s + ((i + 1) & 1) * WSZ;
            #pragma unroll
            for (int j = 0; j < 15; j++) wn[j * 256 + tid] = pf[j];
            if (15 * 256 + tid < WSZ) wn[15 * 256 + tid] = pf[15];
            __syncthreads();
        }
    }

    // epilogue: + bias(o,t) from cumsum, BN, GELU, partial seg-sum
    float tg0 = g_tg[o0 + 0], tg1 = g_tg[o0 + 1], tg2 = g_tg[o0 + 2], tg3 = g_tg[o0 + 3];
    float tb0 = g_tb[o0 + 0], tb1 = g_tb[o0 + 1], tb2 = g_tb[o0 + 2], tb3 = g_tb[o0 + 3];
    float s0 = 0.f, s1 = 0.f, s2 = 0.f, s3 = 0.f;
    #pragma unroll
    for (int r = 0; r < 8; r++) {
        int tl = tx * 8 + r;
        if (tl < SEG) {
            int t = w * SEG + tl;
            int kmin = 31 - t; if (kmin < 0) kmin = 0;
            int kmax = 1155 - t; if (kmax > 62) kmax = 62;
            float b0 = c_s[(o0 + 0) * (KS + 1) + kmax + 1] - c_s[(o0 + 0) * (KS + 1) + kmin];
            float b1 = c_s[(o0 + 1) * (KS + 1) + kmax + 1] - c_s[(o0 + 1) * (KS + 1) + kmin];
            float b2v = c_s[(o0 + 2) * (KS + 1) + kmax + 1] - c_s[(o0 + 2) * (KS + 1) + kmin];
            float b3 = c_s[(o0 + 3) * (KS + 1) + kmax + 1] - c_s[(o0 + 3) * (KS + 1) + kmin];
            float a, bval;
            unpack2(acc0[r], a, bval);
            s0 += gelu_exact(fmaf(a + b0, tg0, tb0));
            s1 += gelu_exact(fmaf(bval + b1, tg1, tb1));
            unpack2(acc1[r], a, bval);
            s2 += gelu_exact(fmaf(a + b2v, tg2, tb2));
            s3 += gelu_exact(fmaf(bval + b3, tg3, tb3));
        }
    }
    // reduce over tx (low 4 lane bits)
    #pragma unroll
    for (int m = 8; m >= 1; m >>= 1) {
        s0 += __shfl_xor_sync(0xffffffffu, s0, m);
        s1 += __shfl_xor_sync(0xffffffffu, s1, m);
        s2 += __shfl_xor_sync(0xffffffffu, s2, m);
        s3 += __shfl_xor_sync(0xffffffffu, s3, m);
    }
    if (tx == 0) {
        const float inv = 1.f / (float)SEG;
        g_pool[bb * (OUTC * WIN) + (o0 + 0) * WIN + w] = s0 * inv;
        g_pool[bb * (OUTC * WIN) + (o0 + 1) * WIN + w] = s1 * inv;
        g_pool[bb * (OUTC * WIN) + (o0 + 2) * WIN + w] = s2 * inv;
        g_pool[bb * (OUTC * WIN) + (o0 + 3) * WIN + w] = s3 * inv;
    }
}

// ============================================================
// Kernel: final FCs + fuse  (1 block, 256 threads, thread = batch row)
// ============================================================
__global__ void k_fc(const float* __restrict__ fc_a_b,
                     const float* __restrict__ fc_b_w, const float* __restrict__ fc_b_b,
                     const float* __restrict__ fc_c_w, const float* __restrict__ fc_c_b,
                     const float* __restrict__ fuse_w, const float* __restrict__ fuse_b,
                     float* __restrict__ out)
{
    __shared__ float sA[NCLS * 576];
    __shared__ float sB[NCLS * 576];
    const int tid = threadIdx.x;
    for (int idx = tid; idx < NCLS * 576; idx += 256) {
        sA[idx] = g_fcA[idx];
        sB[idx] = fc_b_w[idx];
    }
    __syncthreads();
    const int b = tid;
    float la[4], lb[4], lc[4];
    #pragma unroll
    for (int n = 0; n < 4; n++) { la[n] = fc_a_b[n]; lb[n] = fc_b_b[n]; lc[n] = fc_c_b[n]; }
    const float* pA = g_pool + b * 576;
    const float* pB = g_pool + (256 + b) * 576;
    for (int j = 0; j < 576; j++) {
        float va = pA[j], vb = pB[j];
        #pragma unroll
        for (int n = 0; n < 4; n++) {
            la[n] = fmaf(sA[n * 576 + j], va, la[n]);
            lb[n] = fmaf(sB[n * 576 + j], vb, lb[n]);
        }
    }
    for (int c = 0; c < CIN; c++) {
        float v = g_xmean[b * CIN + c];
        #pragma unroll
        for (int n = 0; n < 4; n++) lc[n] = fmaf(fc_c_w[n * CIN + c], v, lc[n]);
    }
    #pragma unroll
    for (int n = 0; n < 4; n++) {
        float o = fuse_b[n];
        #pragma unroll
        for (int m = 0; m < 4; m++) {
            o = fmaf(fuse_w[n * 12 + m], la[m], o);
            o = fmaf(fuse_w[n * 12 + 4 + m], lb[m], o);
            o = fmaf(fuse_w[n * 12 + 8 + m], lc[m], o);
        }
        out[b * 4 + n] = o;
    }
}

// ============================================================
// launch
// ============================================================
extern "C" void kernel_launch(void* const* d_in, const int* in_sizes, int n_in,
                              void* d_out, int out_size) {
    const float* x        = (const float*)d_in[0];
    const float* edge_w   = (const float*)d_in[1];
    const float* sconv_w  = (const float*)d_in[2];
    const float* sbn_g    = (const float*)d_in[3];
    const float* sbn_b    = (const float*)d_in[4];
    const float* sbn_m    = (const float*)d_in[5];
    const float* sbn_v    = (const float*)d_in[6];
    const float* tconv_w  = (const float*)d_in[7];
    const float* tbn_g    = (const float*)d_in[8];
    const float* tbn_b    = (const float*)d_in[9];
    const float* tbn_m    = (const float*)d_in[10];
    const float* tbn_v    = (const float*)d_in[11];
    const float* adj_a    = (const float*)d_in[12];
    const float* adj_b    = (const float*)d_in[13];
    const float* fc_a_w   = (const float*)d_in[14];
    const float* fc_a_b   = (const float*)d_in[15];
    const float* fc_b_w   = (const float*)d_in[16];
    const float* fc_b_b   = (const float*)d_in[17];
    const float* fc_c_w   = (const float*)d_in[18];
    const float* fc_c_b   = (const float*)d_in[19];
    const float* fuse_w   = (const float*)d_in[20];
    const float* fuse_b   = (const float*)d_in[21];
    float* out = (float*)d_out;

    cudaFuncSetAttribute(k_conv2, cudaFuncAttributeMaxDynamicSharedMemorySize, K3_SMEM);

    k_prep<<<1, 256>>>(edge_w, sconv_w, sbn_g, sbn_b, sbn_m, sbn_v,
                       tbn_g, tbn_b, tbn_m, tbn_v, adj_a, adj_b, fc_a_w, out);
    k_wt2<<<(CIN * KS * OUTC + 255) / 256, 256>>>(tconv_w);
    k_bias<<<1, 64>>>(tconv_w);
    k_xb<<<BATCH * CIN, 128>>>(x);
    k_mean<<<BATCH * CIN, 128>>>(x);
    k_conv2<<<dim3(WIN, 2 * BATCH), 256, K3_SMEM>>>(x);
    k_fc<<<1, 256>>>(fc_a_b, fc_b_w, fc_b_b, fc_c_w, fc_c_b, fuse_w, fuse_b, out);
}

// round 7
// speedup vs baseline: 2.4050x; 2.4050x over previous
#include <cuda_runtime.h>
#include <math.h>
#include <stdint.h>

// ---------------- problem constants ----------------
#define BATCH 256
#define CIN   22
#define WIN   9
#define SEG   125
#define OUTC  64
#define KS    63
#define NCLS  4
#define TLEN  1125          // WIN*SEG
#define NEDGE 231           // 22*21/2

// ---------------- device scratch ----------------
__device__ float g_W1[OUTC * CIN];
__device__ float g_sb[OUTC];
__device__ float g_tg[OUTC];
__device__ float g_tb[OUTC];
__device__ float g_Atb2[WIN * WIN];
__device__ float g_fcA[NCLS * OUTC * WIN];
__device__ float g_xb[BATCH * CIN * TLEN];
__device__ float g_w2[CIN * KS * OUTC];          // folded conv weights [c][k][o]
__device__ float g_w3[CIN * 4096];               // tf32 weights in mma-B fragment layout
__device__ float g_C[OUTC * (KS + 1)];           // bias cumsum [o][64]
__device__ float g_pool[2 * BATCH * OUTC * WIN];
__device__ float g_xmean[BATCH * CIN];

// ---------------- helpers ----------------
__device__ __forceinline__ float gelu_exact(float x) {
    return 0.5f * x * (1.f + erff(x * 0.70710678118654752440f));
}
__device__ __forceinline__ uint32_t f2tf(float x) {
    uint32_t r; asm("cvt.rna.tf32.f32 %0, %1;" : "=r"(r) : "f"(x)); return r;
}
// m16n8k8 tf32 warp MMA (row.col), D += A*B
__device__ __forceinline__ void mma8(float* d, const uint32_t* a, uint32_t b0, uint32_t b1) {
    asm volatile(
        "mma.sync.aligned.m16n8k8.row.col.f32.tf32.tf32.f32 "
        "{%0,%1,%2,%3}, {%4,%5,%6,%7}, {%8,%9}, {%0,%1,%2,%3};"
        : "+f"(d[0]), "+f"(d[1]), "+f"(d[2]), "+f"(d[3])
        : "r"(a[0]), "r"(a[1]), "r"(a[2]), "r"(a[3]), "r"(b0), "r"(b1));
}

// ============================================================
// Kernel 0: small precompute
// ============================================================
__global__ void k_prep(const float* __restrict__ ew,
                       const float* __restrict__ sconv_w,
                       const float* __restrict__ sbn_g, const float* __restrict__ sbn_b,
                       const float* __restrict__ sbn_m, const float* __restrict__ sbn_v,
                       const float* __restrict__ tbn_g, const float* __restrict__ tbn_b,
                       const float* __restrict__ tbn_m, const float* __restrict__ tbn_v,
                       const float* __restrict__ adj_after,
                       const float* __restrict__ adj_before,
                       const float* __restrict__ fc_a_w,
                       float* __restrict__ out)
{
    __shared__ float A[484], As[484], As2[484], d22[22];
    __shared__ float Mt[81], At[81], At2[81], d9[9];
    const int tid = threadIdx.x;

    for (int idx = tid; idx < 484; idx += 256) {
        int i = idx / 22, j = idx - i * 22;
        A[idx] = (i == j) ? 1.f : 0.f;
    }
    __syncthreads();
    if (tid < NEDGE) {
        int e = tid, i = 1, base = 0;
        while (e >= base + i) { base += i; i++; }
        int j = e - base;
        float v = ew[tid];
        A[i * 22 + j] = v; A[j * 22 + i] = v;
    }
    __syncthreads();
    if (tid < 22) {
        float s = 0.f;
        for (int j = 0; j < 22; j++) s += A[tid * 22 + j];
        d22[tid] = rsqrtf(s);
    }
    __syncthreads();
    for (int idx = tid; idx < 484; idx += 256) {
        int i = idx / 22, j = idx - i * 22;
        As[idx] = A[idx] * d22[i] * d22[j];
    }
    __syncthreads();
    for (int idx = tid; idx < 484; idx += 256) {
        out[1024 + idx] = As[idx];
        out[1670 + idx] = As[idx];
        int i = idx / 22, j = idx - i * 22;
        float s = 0.f;
        for (int k = 0; k < 22; k++) s += As[i * 22 + k] * As[k * 22 + j];
        As2[idx] = s;
    }
    __syncthreads();

    for (int idx = tid; idx < OUTC * CIN; idx += 256) {
        int o = idx / CIN, c = idx - o * CIN;
        float s = 0.f;
        for (int c2 = 0; c2 < CIN; c2++) s += sconv_w[o * CIN + c2] * As2[c2 * 22 + c];
        float sg = sbn_g[o] * rsqrtf(sbn_v[o] + 1e-5f);
        g_W1[idx] = sg * s;
    }
    if (tid < OUTC) {
        float sg = sbn_g[tid] * rsqrtf(sbn_v[tid] + 1e-5f);
        g_sb[tid] = sbn_b[tid] - sbn_m[tid] * sg;
        float tg = tbn_g[tid] * rsqrtf(tbn_v[tid] + 1e-5f);
        g_tg[tid] = tg;
        g_tb[tid] = tbn_b[tid] - tbn_m[tid] * tg;
    }

    if (tid < 81) {
        int i = tid / 9, j = tid - i * 9;
        Mt[tid] = 0.5f * (adj_after[i * 9 + j] + adj_after[j * 9 + i]);
    }
    __syncthreads();
    if (tid < 9) {
        float s = 0.f;
        for (int j = 0; j < 9; j++) s += Mt[tid * 9 + j];
        d9[tid] = rsqrtf(s);
    }
    __syncthreads();
    if (tid < 81) {
        int i = tid / 9, j = tid - i * 9;
        At[tid] = Mt[tid] * d9[i] * d9[j];
        out[1508 + tid] = At[tid];
    }
    __syncthreads();
    if (tid < 81) {
        int i = tid / 9, j = tid - i * 9;
        float s = 0.f;
        for (int k = 0; k < 9; k++) s += At[i * 9 + k] * At[k * 9 + j];
        At2[tid] = s;
    }
    __syncthreads();
    for (int idx = tid; idx < NCLS * OUTC * WIN; idx += 256) {
        int n = idx / (OUTC * WIN);
        int rem = idx - n * OUTC * WIN;
        int o = rem / WIN, w = rem - o * WIN;
        float s = 0.f;
        for (int wp = 0; wp < 9; wp++) s += fc_a_w[n * 576 + o * 9 + wp] * At2[wp * 9 + w];
        g_fcA[idx] = s;
    }
    __syncthreads();

    if (tid < 81) {
        int i = tid / 9, j = tid - i * 9;
        Mt[tid] = 0.5f * (adj_before[i * 9 + j] + adj_before[j * 9 + i]);
    }
    __syncthreads();
    if (tid < 9) {
        float s = 0.f;
        for (int j = 0; j < 9; j++) s += Mt[tid * 9 + j];
        d9[tid] = rsqrtf(s);
    }
    __syncthreads();
    if (tid < 81) {
        int i = tid / 9, j = tid - i * 9;
        At[tid] = Mt[tid] * d9[i] * d9[j];
        out[1589 + tid] = At[tid];
    }
    __syncthreads();
    if (tid < 81) {
        int i = tid / 9, j = tid - i * 9;
        float s = 0.f;
        for (int k = 0; k < 9; k++) s += At[i * 9 + k] * At[k * 9 + j];
        g_Atb2[tid] = s;
    }
}

// ============================================================
// fold W1 into tconv -> g_w2[c][k][o]
// ============================================================
__global__ void k_wt2(const float* __restrict__ tconv_w) {
    int idx = blockIdx.x * 256 + threadIdx.x;
    if (idx < CIN * KS * OUTC) {
        int c = idx / (KS * OUTC);
        int r = idx - c * (KS * OUTC);
        int k = r / OUTC, o = r - k * OUTC;
        float s = 0.f;
        #pragma unroll 8
        for (int i = 0; i < OUTC; i++)
            s += tconv_w[(o * OUTC + i) * KS + k] * g_W1[i * CIN + c];
        g_w2[idx] = s;
    }
}

// ============================================================
// g_w3: tf32 weights in m16n8k8 B-fragment layout
// idx = c*4096 + chunk*512 + ntile*64 + lane*2 + r
// value = w2[c][k = chunk*8 + (lane&3) + 4r][o = ntile*8 + (lane>>2)], 0 if k>=63
// ============================================================
__global__ void k_wt3() {
    int idx = blockIdx.x * 256 + threadIdx.x;
    if (idx < CIN * 4096) {
        int c = idx >> 12;
        int rem = idx & 4095;
        int chunk = rem >> 9;
        int nt = (rem >> 6) & 7;
        int lane = (rem >> 1) & 31;
        int r = rem & 1;
        int k = chunk * 8 + (lane & 3) + 4 * r;
        int o = nt * 8 + (lane >> 2);
        uint32_t v = (k < KS) ? f2tf(g_w2[(c * KS + k) * OUTC + o]) : 0u;
        ((uint32_t*)g_w3)[idx] = v;
    }
}

// ============================================================
// bias cumsum C[o][kk]
// ============================================================
__global__ void k_bias(const float* __restrict__ tconv_w) {
    int o = threadIdx.x;
    if (o >= OUTC) return;
    float cum = 0.f;
    g_C[o * (KS + 1)] = 0.f;
    for (int k = 0; k < KS; k++) {
        float q = 0.f;
        for (int i = 0; i < OUTC; i++)
            q += tconv_w[(o * OUTC + i) * KS + k] * g_sb[i];
        cum += q;
        g_C[o * (KS + 1) + k + 1] = cum;
    }
}

// ============================================================
// branch-B time mix (view regrouping)
// ============================================================
__global__ void k_xb(const float* __restrict__ x) {
    const int bk = blockIdx.x;
    const int b = bk / CIN, r = bk - b * CIN;
    const int s = threadIdx.x;
    if (s >= SEG) return;
    float v[WIN];
    #pragma unroll
    for (int pp = 0; pp < WIN; pp++) {
        int m = 22 * pp + r;
        int c = m / 9, w = m - c * 9;
        v[pp] = x[((size_t)b * CIN + c) * TLEN + w * SEG + s];
    }
    float* dst = g_xb + ((size_t)b * CIN + r) * TLEN + s;
    #pragma unroll
    for (int p = 0; p < WIN; p++) {
        float a = 0.f;
        #pragma unroll
        for (int pp = 0; pp < WIN; pp++)
            a = fmaf(g_Atb2[p * 9 + pp], v[pp], a);
        dst[p * SEG] = a;
    }
}

// ============================================================
// temporal mean
// ============================================================
__global__ void k_mean(const float* __restrict__ x) {
    __shared__ float red[4];
    const int rc = blockIdx.x;
    const float* src = x + (size_t)rc * TLEN;
    float psum = 0.f;
    for (int idx = threadIdx.x; idx < TLEN; idx += 128) psum += src[idx];
    for (int m = 16; m >= 1; m >>= 1) psum += __shfl_xor_sync(0xffffffffu, psum, m);
    if ((threadIdx.x & 31) == 0) red[threadIdx.x >> 5] = psum;
    __syncthreads();
    if (threadIdx.x == 0)
        g_xmean[rc] = (red[0] + red[1] + red[2] + red[3]) * (1.f / (float)TLEN);
}

// ============================================================
// MAIN: tf32 mma.sync conv + bias + BN + GELU + seg-pool
// grid (9, 512), 128 threads. Warp (wm, wn): 64 t x 32 o.
// D[128t x 64o] = sum_{c,k} y[c][t+k] * W2[c][k][o]
// ============================================================
#define DYN_SMEM ((4224 + 8192 + 128) * 4)   // y tile + 2x weight buf + s_part = 50176B

__global__ void __launch_bounds__(128) k_conv4(const float* __restrict__ x) {
    extern __shared__ float sm[];
    float* y_s = sm;                  // [22][192] tf32 bits
    float* w_s = sm + 4224;           // [2][4096] weight fragments (reused as C table)
    float* s_part = sm + 4224 + 8192; // [2][64]
    __shared__ float s_q[64], s_tg[64], s_tb[64];

    const int w = blockIdx.x;
    const int bb = blockIdx.y;
    const int tid = threadIdx.x;
    const int wid = tid >> 5, lane = tid & 31;
    const int wm = wid & 1, wn = wid >> 1;
    const int g = lane >> 2, tig = lane & 3;
    const int t0 = w * SEG - 31;
    const float* src = ((bb >> 8) ? g_xb : x) + (size_t)(bb & 255) * CIN * TLEN;

    // y halo tile, tf32-converted (187 valid positions, rest zero)
    uint32_t* yu = (uint32_t*)y_s;
    for (int idx = tid; idx < CIN * 192; idx += 128) {
        int c = idx / 192, tt = idx - c * 192;
        int gt = t0 + tt;
        float v = (gt >= 0 && gt < TLEN && tt < 187) ? src[(size_t)c * TLEN + gt] : 0.f;
        yu[idx] = f2tf(v);
    }
    // first channel's weights
    {
        const float4* s4 = (const float4*)g_w3;
        float4* d4 = (float4*)w_s;
        #pragma unroll
        for (int j = 0; j < 8; j++) d4[j * 128 + tid] = s4[j * 128 + tid];
    }
    if (tid < 64) { s_q[tid] = g_C[tid * 64 + 63]; s_tg[tid] = g_tg[tid]; s_tb[tid] = g_tb[tid]; }
    __syncthreads();

    float acc[4][4][4];
    #pragma unroll
    for (int m = 0; m < 4; m++)
        #pragma unroll
        for (int nt = 0; nt < 4; nt++)
            #pragma unroll
            for (int j = 0; j < 4; j++) acc[m][nt][j] = 0.f;

    for (int c = 0; c < CIN; c++) {
        float4 pf[8];
        if (c < CIN - 1) {
            const float4* s4 = (const float4*)(g_w3 + (c + 1) * 4096);
            #pragma unroll
            for (int j = 0; j < 8; j++) pf[j] = s4[j * 128 + tid];
        }
        const uint32_t* ya = yu + c * 192 + wm * 64 + g + tig;
        const float* wb = w_s + (c & 1) * 4096 + wn * 256 + lane * 2;

        #pragma unroll
        for (int chunk = 0; chunk < 8; chunk++) {
            uint32_t a[4][4];
            #pragma unroll
            for (int m = 0; m < 4; m++) {
                const uint32_t* p = ya + m * 16 + chunk * 8;
                a[m][0] = p[0];  // (row g,   col tig)
                a[m][1] = p[8];  // (row g+8, col tig)
                a[m][2] = p[4];  // (row g,   col tig+4)
                a[m][3] = p[12]; // (row g+8, col tig+4)
            }
            #pragma unroll
            for (int nt = 0; nt < 4; nt++) {
                float2 bv = *(const float2*)(wb + chunk * 512 + nt * 64);
                uint32_t b0 = __float_as_uint(bv.x), b1 = __float_as_uint(bv.y);
                #pragma unroll
                for (int m = 0; m < 4; m++)
                    mma8(acc[m][nt], a[m], b0, b1);
            }
        }
        __syncthreads();
        if (c < CIN - 1) {
            float4* d4 = (float4*)(w_s + ((c + 1) & 1) * 4096);
            #pragma unroll
            for (int j = 0; j < 8; j++) d4[j * 128 + tid] = pf[j];
            __syncthreads();
        }
    }

    // ---- epilogue ----
    const bool edge = (w == 0) || (w == WIN - 1);
    if (edge) {
        for (int j = tid; j < 4096; j += 128) w_s[j] = g_C[j];
    }
    __syncthreads();

    const int tg_base = w * SEG;
    #pragma unroll
    for (int nt = 0; nt < 4; nt++) {
        int o0 = wn * 32 + nt * 8 + 2 * tig, o1 = o0 + 1;
        float tg0 = s_tg[o0], tb0_ = s_tb[o0], tg1 = s_tg[o1], tb1_ = s_tb[o1];
        float q0 = s_q[o0], q1 = s_q[o1];
        float s0 = 0.f, s1 = 0.f;
        #pragma unroll
        for (int m = 0; m < 4; m++) {
            int t_a = wm * 64 + m * 16 + g;
            int t_b = t_a + 8;
            float b0a = q0, b1a = q1, b0b = q0, b1b = q1;
            if (edge) {
                int tag = tg_base + t_a;
                int kmin = 31 - tag; kmin = kmin < 0 ? 0 : kmin;
                int kx = 1156 - tag; kx = kx > 63 ? 63 : kx;
                b0a = w_s[o0 * 64 + kx] - w_s[o0 * 64 + kmin];
                b1a = w_s[o1 * 64 + kx] - w_s[o1 * 64 + kmin];
                int tbg = tag + 8;
                int kminb = 31 - tbg; kminb = kminb < 0 ? 0 : kminb;
                int kxb = 1156 - tbg; kxb = kxb > 63 ? 63 : kxb;
                b0b = w_s[o0 * 64 + kxb] - w_s[o0 * 64 + kminb];
                b1b = w_s[o1 * 64 + kxb] - w_s[o1 * 64 + kminb];
            }
            if (t_a < SEG) {
                s0 += gelu_exact(fmaf(acc[m][nt][0] + b0a, tg0, tb0_));
                s1 += gelu_exact(fmaf(acc[m][nt][1] + b1a, tg1, tb1_));
            }
            if (t_b < SEG) {
                s0 += gelu_exact(fmaf(acc[m][nt][2] + b0b, tg0, tb0_));
                s1 += gelu_exact(fmaf(acc[m][nt][3] + b1b, tg1, tb1_));
            }
        }
        s0 += __shfl_xor_sync(0xffffffffu, s0, 4);
        s0 += __shfl_xor_sync(0xffffffffu, s0, 8);
        s0 += __shfl_xor_sync(0xffffffffu, s0, 16);
        s1 += __shfl_xor_sync(0xffffffffu, s1, 4);
        s1 += __shfl_xor_sync(0xffffffffu, s1, 8);
        s1 += __shfl_xor_sync(0xffffffffu, s1, 16);
        if (g == 0) {
            s_part[wm * 64 + o0] = s0;
            s_part[wm * 64 + o1] = s1;
        }
    }
    __syncthreads();
    if (tid < 64)
        g_pool[bb * 576 + tid * 9 + w] = (s_part[tid] + s_part[64 + tid]) * 0.008f;
}

// ============================================================
// final FCs + fuse
// ============================================================
__global__ void k_fc(const float* __restrict__ fc_a_b,
                     const float* __restrict__ fc_b_w, const float* __restrict__ fc_b_b,
                     const float* __restrict__ fc_c_w, const float* __restrict__ fc_c_b,
                     const float* __restrict__ fuse_w, const float* __restrict__ fuse_b,
                     float* __restrict__ out)
{
    __shared__ float sA[NCLS * 576];
    __shared__ float sB[NCLS * 576];
    const int tid = threadIdx.x;
    for (int idx = tid; idx < NCLS * 576; idx += 256) {
        sA[idx] = g_fcA[idx];
        sB[idx] = fc_b_w[idx];
    }
    __syncthreads();
    const int b = tid;
    float la[4], lb[4], lc[4];
    #pragma unroll
    for (int n = 0; n < 4; n++) { la[n] = fc_a_b[n]; lb[n] = fc_b_b[n]; lc[n] = fc_c_b[n]; }
    const float* pA = g_pool + b * 576;
    const float* pB = g_pool + (256 + b) * 576;
    for (int j = 0; j < 576; j++) {
        float va = pA[j], vb = pB[j];
        #pragma unroll
        for (int n = 0; n < 4; n++) {
            la[n] = fmaf(sA[n * 576 + j], va, la[n]);
            lb[n] = fmaf(sB[n * 576 + j], vb, lb[n]);
        }
    }
    for (int c = 0; c < CIN; c++) {
        float v = g_xmean[b * CIN + c];
        #pragma unroll
        for (int n = 0; n < 4; n++) lc[n] = fmaf(fc_c_w[n * CIN + c], v, lc[n]);
    }
    #pragma unroll
    for (int n = 0; n < 4; n++) {
        float o = fuse_b[n];
        #pragma unroll
        for (int m = 0; m < 4; m++) {
            o = fmaf(fuse_w[n * 12 + m], la[m], o);
            o = fmaf(fuse_w[n * 12 + 4 + m], lb[m], o);
            o = fmaf(fuse_w[n * 12 + 8 + m], lc[m], o);
        }
        out[b * 4 + n] = o;
    }
}

// ============================================================
// launch
// ============================================================
extern "C" void kernel_launch(void* const* d_in, const int* in_sizes, int n_in,
                              void* d_out, int out_size) {
    const float* x        = (const float*)d_in[0];
    const float* edge_w   = (const float*)d_in[1];
    const float* sconv_w  = (const float*)d_in[2];
    const float* sbn_g    = (const float*)d_in[3];
    const float* sbn_b    = (const float*)d_in[4];
    const float* sbn_m    = (const float*)d_in[5];
    const float* sbn_v    = (const float*)d_in[6];
    const float* tconv_w  = (const float*)d_in[7];
    const float* tbn_g    = (const float*)d_in[8];
    const float* tbn_b    = (const float*)d_in[9];
    const float* tbn_m    = (const float*)d_in[10];
    const float* tbn_v    = (const float*)d_in[11];
    const float* adj_a    = (const float*)d_in[12];
    const float* adj_b    = (const float*)d_in[13];
    const float* fc_a_w   = (const float*)d_in[14];
    const float* fc_a_b   = (const float*)d_in[15];
    const float* fc_b_w   = (const float*)d_in[16];
    const float* fc_b_b   = (const float*)d_in[17];
    const float* fc_c_w   = (const float*)d_in[18];
    const float* fc_c_b   = (const float*)d_in[19];
    const float* fuse_w   = (const float*)d_in[20];
    const float* fuse_b   = (const float*)d_in[21];
    float* out = (float*)d_out;

    cudaFuncSetAttribute(k_conv4, cudaFuncAttributeMaxDynamicSharedMemorySize, DYN_SMEM);

    k_prep<<<1, 256>>>(edge_w, sconv_w, sbn_g, sbn_b, sbn_m, sbn_v,
                       tbn_g, tbn_b, tbn_m, tbn_v, adj_a, adj_b, fc_a_w, out);
    k_wt2<<<(CIN * KS * OUTC + 255) / 256, 256>>>(tconv_w);
    k_wt3<<<(CIN * 4096 + 255) / 256, 256>>>();
    k_bias<<<1, 64>>>(tconv_w);
    k_xb<<<BATCH * CIN, 128>>>(x);
    k_mean<<<BATCH * CIN, 128>>>(x);
    k_conv4<<<dim3(WIN, 2 * BATCH), 128, DYN_SMEM>>>(x);
    k_fc<<<1, 256>>>(fc_a_b, fc_b_w, fc_b_b, fc_c_w, fc_c_b, fuse_w, fuse_b, out);
}

// round 8
// speedup vs baseline: 2.8551x; 1.1871x over previous
#include <cuda_runtime.h>
#include <math.h>
#include <stdint.h>

// ---------------- problem constants ----------------
#define BATCH 256
#define CIN   22
#define WIN   9
#define SEG   125
#define OUTC  64
#define KS    63
#define NCLS  4
#define TLEN  1125          // WIN*SEG
#define NEDGE 231           // 22*21/2

// ---------------- device scratch ----------------
__device__ float g_W1[OUTC * CIN];
__device__ float g_sb[OUTC];
__device__ float g_tg[OUTC];
__device__ float g_tb[OUTC];
__device__ float g_Atb2[WIN * WIN];
__device__ float g_fcA[NCLS * OUTC * WIN];
__device__ float g_xb[BATCH * CIN * TLEN];
__device__ float g_w2[CIN * KS * OUTC];          // folded conv weights [c][k][o]
__device__ float g_w3[CIN * 4096];               // tf32 weights in mma-B fragment layout
__device__ float g_q[OUTC * KS];                 // per-(o,k) bias contribution
__device__ float g_C[OUTC * (KS + 1)];           // bias cumsum [o][64]
__device__ float g_pool[2 * BATCH * OUTC * WIN];
__device__ float g_xmean[BATCH * CIN];

// ---------------- helpers ----------------
__device__ __forceinline__ float gelu_exact(float x) {
    return 0.5f * x * (1.f + erff(x * 0.70710678118654752440f));
}
__device__ __forceinline__ uint32_t f2tf(float x) {
    uint32_t r; asm("cvt.rna.tf32.f32 %0, %1;" : "=r"(r) : "f"(x)); return r;
}
// m16n8k8 tf32 warp MMA (row.col), D += A*B
__device__ __forceinline__ void mma8(float* d, const uint32_t* a, uint32_t b0, uint32_t b1) {
    asm volatile(
        "mma.sync.aligned.m16n8k8.row.col.f32.tf32.tf32.f32 "
        "{%0,%1,%2,%3}, {%4,%5,%6,%7}, {%8,%9}, {%0,%1,%2,%3};"
        : "+f"(d[0]), "+f"(d[1]), "+f"(d[2]), "+f"(d[3])
        : "r"(a[0]), "r"(a[1]), "r"(a[2]), "r"(a[3]), "r"(b0), "r"(b1));
}

// ============================================================
// Kernel 0: small precompute
// ============================================================
__global__ void k_prep(const float* __restrict__ ew,
                       const float* __restrict__ sconv_w,
                       const float* __restrict__ sbn_g, const float* __restrict__ sbn_b,
                       const float* __restrict__ sbn_m, const float* __restrict__ sbn_v,
                       const float* __restrict__ tbn_g, const float* __restrict__ tbn_b,
                       const float* __restrict__ tbn_m, const float* __restrict__ tbn_v,
                       const float* __restrict__ adj_after,
                       const float* __restrict__ adj_before,
                       const float* __restrict__ fc_a_w,
                       float* __restrict__ out)
{
    __shared__ float A[484], As[484], As2[484], d22[22];
    __shared__ float Mt[81], At[81], At2[81], d9[9];
    const int tid = threadIdx.x;

    for (int idx = tid; idx < 484; idx += 256) {
        int i = idx / 22, j = idx - i * 22;
        A[idx] = (i == j) ? 1.f : 0.f;
    }
    __syncthreads();
    if (tid < NEDGE) {
        int e = tid, i = 1, base = 0;
        while (e >= base + i) { base += i; i++; }
        int j = e - base;
        float v = ew[tid];
        A[i * 22 + j] = v; A[j * 22 + i] = v;
    }
    __syncthreads();
    if (tid < 22) {
        float s = 0.f;
        for (int j = 0; j < 22; j++) s += A[tid * 22 + j];
        d22[tid] = rsqrtf(s);
    }
    __syncthreads();
    for (int idx = tid; idx < 484; idx += 256) {
        int i = idx / 22, j = idx - i * 22;
        As[idx] = A[idx] * d22[i] * d22[j];
    }
    __syncthreads();
    for (int idx = tid; idx < 484; idx += 256) {
        out[1024 + idx] = As[idx];
        out[1670 + idx] = As[idx];
        int i = idx / 22, j = idx - i * 22;
        float s = 0.f;
        for (int k = 0; k < 22; k++) s += As[i * 22 + k] * As[k * 22 + j];
        As2[idx] = s;
    }
    __syncthreads();

    for (int idx = tid; idx < OUTC * CIN; idx += 256) {
        int o = idx / CIN, c = idx - o * CIN;
        float s = 0.f;
        for (int c2 = 0; c2 < CIN; c2++) s += sconv_w[o * CIN + c2] * As2[c2 * 22 + c];
        float sg = sbn_g[o] * rsqrtf(sbn_v[o] + 1e-5f);
        g_W1[idx] = sg * s;
    }
    if (tid < OUTC) {
        float sg = sbn_g[tid] * rsqrtf(sbn_v[tid] + 1e-5f);
        g_sb[tid] = sbn_b[tid] - sbn_m[tid] * sg;
        float tg = tbn_g[tid] * rsqrtf(tbn_v[tid] + 1e-5f);
        g_tg[tid] = tg;
        g_tb[tid] = tbn_b[tid] - tbn_m[tid] * tg;
    }

    if (tid < 81) {
        int i = tid / 9, j = tid - i * 9;
        Mt[tid] = 0.5f * (adj_after[i * 9 + j] + adj_after[j * 9 + i]);
    }
    __syncthreads();
    if (tid < 9) {
        float s = 0.f;
        for (int j = 0; j < 9; j++) s += Mt[tid * 9 + j];
        d9[tid] = rsqrtf(s);
    }
    __syncthreads();
    if (tid < 81) {
        int i = tid / 9, j = tid - i * 9;
        At[tid] = Mt[tid] * d9[i] * d9[j];
        out[1508 + tid] = At[tid];
    }
    __syncthreads();
    if (tid < 81) {
        int i = tid / 9, j = tid - i * 9;
        float s = 0.f;
        for (int k = 0; k < 9; k++) s += At[i * 9 + k] * At[k * 9 + j];
        At2[tid] = s;
    }
    __syncthreads();
    for (int idx = tid; idx < NCLS * OUTC * WIN; idx += 256) {
        int n = idx / (OUTC * WIN);
        int rem = idx - n * OUTC * WIN;
        int o = rem / WIN, w = rem - o * WIN;
        float s = 0.f;
        for (int wp = 0; wp < 9; wp++) s += fc_a_w[n * 576 + o * 9 + wp] * At2[wp * 9 + w];
        g_fcA[idx] = s;
    }
    __syncthreads();

    if (tid < 81) {
        int i = tid / 9, j = tid - i * 9;
        Mt[tid] = 0.5f * (adj_before[i * 9 + j] + adj_before[j * 9 + i]);
    }
    __syncthreads();
    if (tid < 9) {
        float s = 0.f;
        for (int j = 0; j < 9; j++) s += Mt[tid * 9 + j];
        d9[tid] = rsqrtf(s);
    }
    __syncthreads();
    if (tid < 81) {
        int i = tid / 9, j = tid - i * 9;
        At[tid] = Mt[tid] * d9[i] * d9[j];
        out[1589 + tid] = At[tid];
    }
    __syncthreads();
    if (tid < 81) {
        int i = tid / 9, j = tid - i * 9;
        float s = 0.f;
        for (int k = 0; k < 9; k++) s += At[i * 9 + k] * At[k * 9 + j];
        g_Atb2[tid] = s;
    }
}

// ============================================================
// fold W1 into tconv -> g_w2[c][k][o]
// ============================================================
__global__ void k_wt2(const float* __restrict__ tconv_w) {
    int idx = blockIdx.x * 256 + threadIdx.x;
    if (idx < CIN * KS * OUTC) {
        int c = idx / (KS * OUTC);
        int r = idx - c * (KS * OUTC);
        int k = r / OUTC, o = r - k * OUTC;
        float s = 0.f;
        #pragma unroll 8
        for (int i = 0; i < OUTC; i++)
            s += tconv_w[(o * OUTC + i) * KS + k] * g_W1[i * CIN + c];
        g_w2[idx] = s;
    }
}

// ============================================================
// g_w3: tf32 weights in m16n8k8 B-fragment layout
// idx = c*4096 + chunk*512 + ntile*64 + lane*2 + r
// value = w2[c][k = chunk*8 + (lane&3) + 4r][o = ntile*8 + (lane>>2)], 0 if k>=63
// ============================================================
__global__ void k_wt3() {
    int idx = blockIdx.x * 256 + threadIdx.x;
    if (idx < CIN * 4096) {
        int c = idx >> 12;
        int rem = idx & 4095;
        int chunk = rem >> 9;
        int nt = (rem >> 6) & 7;
        int lane = (rem >> 1) & 31;
        int r = rem & 1;
        int k = chunk * 8 + (lane & 3) + 4 * r;
        int o = nt * 8 + (lane >> 2);
        uint32_t v = (k < KS) ? f2tf(g_w2[(c * KS + k) * OUTC + o]) : 0u;
        ((uint32_t*)g_w3)[idx] = v;
    }
}

// ============================================================
// bias fold, parallel: q[o][k] = sum_i w[o][i][k]*sb[i]
// ============================================================
__global__ void k_biasq(const float* __restrict__ tconv_w) {
    int idx = blockIdx.x * 256 + threadIdx.x;     // o*KS + k
    if (idx < OUTC * KS) {
        int o = idx / KS, k = idx - o * KS;
        const float* wp = tconv_w + o * OUTC * KS + k;
        float s = 0.f;
        #pragma unroll 8
        for (int i = 0; i < OUTC; i++)
            s += wp[i * KS] * g_sb[i];
        g_q[idx] = s;
    }
}

// cumsum per o (tiny, L2-hot)
__global__ void k_bias2() {
    int o = threadIdx.x;
    if (o >= OUTC) return;
    float cum = 0.f;
    g_C[o * (KS + 1)] = 0.f;
    for (int k = 0; k < KS; k++) {
        cum += g_q[o * KS + k];
        g_C[o * (KS + 1) + k + 1] = cum;
    }
}

// ============================================================
// branch-B time mix (view regrouping)
// ============================================================
__global__ void k_xb(const float* __restrict__ x) {
    const int bk = blockIdx.x;
    const int b = bk / CIN, r = bk - b * CIN;
    const int s = threadIdx.x;
    if (s >= SEG) return;
    float v[WIN];
    #pragma unroll
    for (int pp = 0; pp < WIN; pp++) {
        int m = 22 * pp + r;
        int c = m / 9, w = m - c * 9;
        v[pp] = x[((size_t)b * CIN + c) * TLEN + w * SEG + s];
    }
    float* dst = g_xb + ((size_t)b * CIN + r) * TLEN + s;
    #pragma unroll
    for (int p = 0; p < WIN; p++) {
        float a = 0.f;
        #pragma unroll
        for (int pp = 0; pp < WIN; pp++)
            a = fmaf(g_Atb2[p * 9 + pp], v[pp], a);
        dst[p * SEG] = a;
    }
}

// ============================================================
// temporal mean
// ============================================================
__global__ void k_mean(const float* __restrict__ x) {
    __shared__ float red[4];
    const int rc = blockIdx.x;
    const float* src = x + (size_t)rc * TLEN;
    float psum = 0.f;
    for (int idx = threadIdx.x; idx < TLEN; idx += 128) psum += src[idx];
    for (int m = 16; m >= 1; m >>= 1) psum += __shfl_xor_sync(0xffffffffu, psum, m);
    if ((threadIdx.x & 31) == 0) red[threadIdx.x >> 5] = psum;
    __syncthreads();
    if (threadIdx.x == 0)
        g_xmean[rc] = (red[0] + red[1] + red[2] + red[3]) * (1.f / (float)TLEN);
}

// ============================================================
// MAIN: tf32 mma.sync conv + bias + BN + GELU + seg-pool
// grid (9, 512), 128 threads. Warp (wm, wn): 64 t x 32 o.
// D[128t x 64o] = sum_{c,k} y[c][t+k] * W2[c][k][o]
// ============================================================
#define DYN_SMEM ((4224 + 8192 + 128) * 4)   // y tile + 2x weight buf + s_part = 50176B

__global__ void __launch_bounds__(128) k_conv4(const float* __restrict__ x) {
    extern __shared__ float sm[];
    float* y_s = sm;                  // [22][192] tf32 bits
    float* w_s = sm + 4224;           // [2][4096] weight fragments (reused as C table)
    float* s_part = sm + 4224 + 8192; // [2][64]
    __shared__ float s_q[64], s_tg[64], s_tb[64];

    const int w = blockIdx.x;
    const int bb = blockIdx.y;
    const int tid = threadIdx.x;
    const int wid = tid >> 5, lane = tid & 31;
    const int wm = wid & 1, wn = wid >> 1;
    const int g = lane >> 2, tig = lane & 3;
    const int t0 = w * SEG - 31;
    const float* src = ((bb >> 8) ? g_xb : x) + (size_t)(bb & 255) * CIN * TLEN;

    // y halo tile, tf32-converted (187 valid positions, rest zero)
    uint32_t* yu = (uint32_t*)y_s;
    for (int idx = tid; idx < CIN * 192; idx += 128) {
        int c = idx / 192, tt = idx - c * 192;
        int gt = t0 + tt;
        float v = (gt >= 0 && gt < TLEN && tt < 187) ? src[(size_t)c * TLEN + gt] : 0.f;
        yu[idx] = f2tf(v);
    }
    // first channel's weights
    {
        const float4* s4 = (const float4*)g_w3;
        float4* d4 = (float4*)w_s;
        #pragma unroll
        for (int j = 0; j < 8; j++) d4[j * 128 + tid] = s4[j * 128 + tid];
    }
    if (tid < 64) { s_q[tid] = g_C[tid * 64 + 63]; s_tg[tid] = g_tg[tid]; s_tb[tid] = g_tb[tid]; }
    __syncthreads();

    float acc[4][4][4];
    #pragma unroll
    for (int m = 0; m < 4; m++)
        #pragma unroll
        for (int nt = 0; nt < 4; nt++)
            #pragma unroll
            for (int j = 0; j < 4; j++) acc[m][nt][j] = 0.f;

    for (int c = 0; c < CIN; c++) {
        float4 pf[8];
        if (c < CIN - 1) {
            const float4* s4 = (const float4*)(g_w3 + (c + 1) * 4096);
            #pragma unroll
            for (int j = 0; j < 8; j++) pf[j] = s4[j * 128 + tid];
        }
        const uint32_t* ya = yu + c * 192 + wm * 64 + g + tig;
        const float* wb = w_s + (c & 1) * 4096 + wn * 256 + lane * 2;

        #pragma unroll
        for (int chunk = 0; chunk < 8; chunk++) {
            uint32_t a[4][4];
            #pragma unroll
            for (int m = 0; m < 4; m++) {
                const uint32_t* p = ya + m * 16 + chunk * 8;
                a[m][0] = p[0];  // (row g,   col tig)
                a[m][1] = p[8];  // (row g+8, col tig)
                a[m][2] = p[4];  // (row g,   col tig+4)
                a[m][3] = p[12]; // (row g+8, col tig+4)
            }
            #pragma unroll
            for (int nt = 0; nt < 4; nt++) {
                float2 bv = *(const float2*)(wb + chunk * 512 + nt * 64);
                uint32_t b0 = __float_as_uint(bv.x), b1 = __float_as_uint(bv.y);
                #pragma unroll
                for (int m = 0; m < 4; m++)
                    mma8(acc[m][nt], a[m], b0, b1);
            }
        }
        __syncthreads();
        if (c < CIN - 1) {
            float4* d4 = (float4*)(w_s + ((c + 1) & 1) * 4096);
            #pragma unroll
            for (int j = 0; j < 8; j++) d4[j * 128 + tid] = pf[j];
            __syncthreads();
        }
    }

    // ---- epilogue ----
    const bool edge = (w == 0) || (w == WIN - 1);
    if (edge) {
        for (int j = tid; j < 4096; j += 128) w_s[j] = g_C[j];
    }
    __syncthreads();

    const int tg_base = w * SEG;
    #pragma unroll
    for (int nt = 0; nt < 4; nt++) {
        int o0 = wn * 32 + nt * 8 + 2 * tig, o1 = o0 + 1;
        float tg0 = s_tg[o0], tb0_ = s_tb[o0], tg1 = s_tg[o1], tb1_ = s_tb[o1];
        float q0 = s_q[o0], q1 = s_q[o1];
        float s0 = 0.f, s1 = 0.f;
        #pragma unroll
        for (int m = 0; m < 4; m++) {
            int t_a = wm * 64 + m * 16 + g;
            int t_b = t_a + 8;
            float b0a = q0, b1a = q1, b0b = q0, b1b = q1;
            if (edge) {
                int tag = tg_base + t_a;
                int kmin = 31 - tag; kmin = kmin < 0 ? 0 : kmin;
                int kx = 1156 - tag; kx = kx > 63 ? 63 : kx;
                b0a = w_s[o0 * 64 + kx] - w_s[o0 * 64 + kmin];
                b1a = w_s[o1 * 64 + kx] - w_s[o1 * 64 + kmin];
                int tbg = tag + 8;
                int kminb = 31 - tbg; kminb = kminb < 0 ? 0 : kminb;
                int kxb = 1156 - tbg; kxb = kxb > 63 ? 63 : kxb;
                b0b = w_s[o0 * 64 + kxb] - w_s[o0 * 64 + kminb];
                b1b = w_s[o1 * 64 + kxb] - w_s[o1 * 64 + kminb];
            }
            if (t_a < SEG) {
                s0 += gelu_exact(fmaf(acc[m][nt][0] + b0a, tg0, tb0_));
                s1 += gelu_exact(fmaf(acc[m][nt][1] + b1a, tg1, tb1_));
            }
            if (t_b < SEG) {
                s0 += gelu_exact(fmaf(acc[m][nt][2] + b0b, tg0, tb0_));
                s1 += gelu_exact(fmaf(acc[m][nt][3] + b1b, tg1, tb1_));
            }
        }
        s0 += __shfl_xor_sync(0xffffffffu, s0, 4);
        s0 += __shfl_xor_sync(0xffffffffu, s0, 8);
        s0 += __shfl_xor_sync(0xffffffffu, s0, 16);
        s1 += __shfl_xor_sync(0xffffffffu, s1, 4);
        s1 += __shfl_xor_sync(0xffffffffu, s1, 8);
        s1 += __shfl_xor_sync(0xffffffffu, s1, 16);
        if (g == 0) {
            s_part[wm * 64 + o0] = s0;
            s_part[wm * 64 + o1] = s1;
        }
    }
    __syncthreads();
    if (tid < 64)
        g_pool[bb * 576 + tid * 9 + w] = (s_part[tid] + s_part[64 + tid]) * 0.008f;
}

// ============================================================
// final FCs + fuse
// ============================================================
__global__ void k_fc(const float* __restrict__ fc_a_b,
                     const float* __restrict__ fc_b_w, const float* __restrict__ fc_b_b,
                     const float* __restrict__ fc_c_w, const float* __restrict__ fc_c_b,
                     const float* __restrict__ fuse_w, const float* __restrict__ fuse_b,
                     float* __restrict__ out)
{
    __shared__ float sA[NCLS * 576];
    __shared__ float sB[NCLS * 576];
    const int tid = threadIdx.x;
    for (int idx = tid; idx < NCLS * 576; idx += 256) {
        sA[idx] = g_fcA[idx];
        sB[idx] = fc_b_w[idx];
    }
    __syncthreads();
    const int b = tid;
    float la[4], lb[4], lc[4];
    #pragma unroll
    for (int n = 0; n < 4; n++) { la[n] = fc_a_b[n]; lb[n] = fc_b_b[n]; lc[n] = fc_c_b[n]; }
    const float* pA = g_pool + b * 576;
    const float* pB = g_pool + (256 + b) * 576;
    for (int j = 0; j < 576; j++) {
        float va = pA[j], vb = pB[j];
        #pragma unroll
        for (int n = 0; n < 4; n++) {
            la[n] = fmaf(sA[n * 576 + j], va, la[n]);
            lb[n] = fmaf(sB[n * 576 + j], vb, lb[n]);
        }
    }
    for (int c = 0; c < CIN; c++) {
        float v = g_xmean[b * CIN + c];
        #pragma unroll
        for (int n = 0; n < 4; n++) lc[n] = fmaf(fc_c_w[n * CIN + c], v, lc[n]);
    }
    #pragma unroll
    for (int n = 0; n < 4; n++) {
        float o = fuse_b[n];
        #pragma unroll
        for (int m = 0; m < 4; m++) {
            o = fmaf(fuse_w[n * 12 + m], la[m], o);
            o = fmaf(fuse_w[n * 12 + 4 + m], lb[m], o);
            o = fmaf(fuse_w[n * 12 + 8 + m], lc[m], o);
        }
        out[b * 4 + n] = o;
    }
}

// ============================================================
// launch
// ============================================================
extern "C" void kernel_launch(void* const* d_in, const int* in_sizes, int n_in,
                              void* d_out, int out_size) {
    const float* x        = (const float*)d_in[0];
    const float* edge_w   = (const float*)d_in[1];
    const float* sconv_w  = (const float*)d_in[2];
    const float* sbn_g    = (const float*)d_in[3];
    const float* sbn_b    = (const float*)d_in[4];
    const float* sbn_m    = (const float*)d_in[5];
    const float* sbn_v    = (const float*)d_in[6];
    const float* tconv_w  = (const float*)d_in[7];
    const float* tbn_g    = (const float*)d_in[8];
    const float* tbn_b    = (const float*)d_in[9];
    const float* tbn_m    = (const float*)d_in[10];
    const float* tbn_v    = (const float*)d_in[11];
    const float* adj_a    = (const float*)d_in[12];
    const float* adj_b    = (const float*)d_in[13];
    const float* fc_a_w   = (const float*)d_in[14];
    const float* fc_a_b   = (const float*)d_in[15];
    const float* fc_b_w   = (const float*)d_in[16];
    const float* fc_b_b   = (const float*)d_in[17];
    const float* fc_c_w   = (const float*)d_in[18];
    const float* fc_c_b   = (const float*)d_in[19];
    const float* fuse_w   = (const float*)d_in[20];
    const float* fuse_b   = (const float*)d_in[21];
    float* out = (float*)d_out;

    cudaFuncSetAttribute(k_conv4, cudaFuncAttributeMaxDynamicSharedMemorySize, DYN_SMEM);

    k_prep<<<1, 256>>>(edge_w, sconv_w, sbn_g, sbn_b, sbn_m, sbn_v,
                       tbn_g, tbn_b, tbn_m, tbn_v, adj_a, adj_b, fc_a_w, out);
    k_wt2<<<(CIN * KS * OUTC + 255) / 256, 256>>>(tconv_w);
    k_wt3<<<(CIN * 4096 + 255) / 256, 256>>>();
    k_biasq<<<(OUTC * KS + 255) / 256, 256>>>(tconv_w);
    k_bias2<<<1, 64>>>();
    k_xb<<<BATCH * CIN, 128>>>(x);
    k_mean<<<BATCH * CIN, 128>>>(x);
    k_conv4<<<dim3(WIN, 2 * BATCH), 128, DYN_SMEM>>>(x);
    k_fc<<<1, 256>>>(fc_a_b, fc_b_w, fc_b_b, fc_c_w, fc_c_b, fuse_w, fuse_b, out);
}

// round 9
// speedup vs baseline: 4.4083x; 1.5440x over previous
#include <cuda_runtime.h>
#include <math.h>
#include <stdint.h>

// ---------------- problem constants ----------------
#define BATCH 256
#define CIN   22
#define WIN   9
#define SEG   125
#define OUTC  64
#define KS    63
#define NCLS  4
#define TLEN  1125          // WIN*SEG
#define NEDGE 231           // 22*21/2

// ---------------- device scratch ----------------
__device__ float g_W1[OUTC * CIN];
__device__ float g_sb[OUTC];
__device__ float g_tg[OUTC];
__device__ float g_tb[OUTC];
__device__ float g_Atb2[WIN * WIN];
__device__ float g_fcA[NCLS * OUTC * WIN];
__device__ float g_xb[BATCH * CIN * TLEN];
__device__ float g_w2[CIN * KS * OUTC];          // folded conv weights [c][k][o]
__device__ float g_w3[CIN * 2048];               // bf16x2 weights in m16n8k16 B-frag layout
__device__ float g_q[OUTC * KS];                 // per-(o,k) bias contribution
__device__ float g_C[OUTC * (KS + 1)];           // bias cumsum [o][64]
__device__ float g_pool[576 * 2 * BATCH];        // TRANSPOSED: [o*9+w][bb]
__device__ float g_xmean[BATCH * CIN];

// ---------------- helpers ----------------
__device__ __forceinline__ float gelu_exact(float x) {
    return 0.5f * x * (1.f + erff(x * 0.70710678118654752440f));
}
// pack two floats into bf16x2: lo -> bits[15:0], hi -> bits[31:16]
__device__ __forceinline__ uint32_t pack_bf(float lo, float hi) {
    uint32_t r; asm("cvt.rn.bf16x2.f32 %0, %1, %2;" : "=r"(r) : "f"(hi), "f"(lo)); return r;
}
// m16n8k16 bf16 warp MMA (row.col), D += A*B
__device__ __forceinline__ void mma16(float* d, const uint32_t* a, uint32_t b0, uint32_t b1) {
    asm volatile(
        "mma.sync.aligned.m16n8k16.row.col.f32.bf16.bf16.f32 "
        "{%0,%1,%2,%3}, {%4,%5,%6,%7}, {%8,%9}, {%0,%1,%2,%3};"
        : "+f"(d[0]), "+f"(d[1]), "+f"(d[2]), "+f"(d[3])
        : "r"(a[0]), "r"(a[1]), "r"(a[2]), "r"(a[3]), "r"(b0), "r"(b1));
}

// ============================================================
// Kernel 0: small precompute
// ============================================================
__global__ void k_prep(const float* __restrict__ ew,
                       const float* __restrict__ sconv_w,
                       const float* __restrict__ sbn_g, const float* __restrict__ sbn_b,
                       const float* __restrict__ sbn_m, const float* __restrict__ sbn_v,
                       const float* __restrict__ tbn_g, const float* __restrict__ tbn_b,
                       const float* __restrict__ tbn_m, const float* __restrict__ tbn_v,
                       const float* __restrict__ adj_after,
                       const float* __restrict__ adj_before,
                       const float* __restrict__ fc_a_w,
                       float* __restrict__ out)
{
    __shared__ float A[484], As[484], As2[484], d22[22];
    __shared__ float Mt[81], At[81], At2[81], d9[9];
    const int tid = threadIdx.x;

    for (int idx = tid; idx < 484; idx += 256) {
        int i = idx / 22, j = idx - i * 22;
        A[idx] = (i == j) ? 1.f : 0.f;
    }
    __syncthreads();
    if (tid < NEDGE) {
        int e = tid, i = 1, base = 0;
        while (e >= base + i) { base += i; i++; }
        int j = e - base;
        float v = ew[tid];
        A[i * 22 + j] = v; A[j * 22 + i] = v;
    }
    __syncthreads();
    if (tid < 22) {
        float s = 0.f;
        for (int j = 0; j < 22; j++) s += A[tid * 22 + j];
        d22[tid] = rsqrtf(s);
    }
    __syncthreads();
    for (int idx = tid; idx < 484; idx += 256) {
        int i = idx / 22, j = idx - i * 22;
        As[idx] = A[idx] * d22[i] * d22[j];
    }
    __syncthreads();
    for (int idx = tid; idx < 484; idx += 256) {
        out[1024 + idx] = As[idx];
        out[1670 + idx] = As[idx];
        int i = idx / 22, j = idx - i * 22;
        float s = 0.f;
        for (int k = 0; k < 22; k++) s += As[i * 22 + k] * As[k * 22 + j];
        As2[idx] = s;
    }
    __syncthreads();

    for (int idx = tid; idx < OUTC * CIN; idx += 256) {
        int o = idx / CIN, c = idx - o * CIN;
        float s = 0.f;
        for (int c2 = 0; c2 < CIN; c2++) s += sconv_w[o * CIN + c2] * As2[c2 * 22 + c];
        float sg = sbn_g[o] * rsqrtf(sbn_v[o] + 1e-5f);
        g_W1[idx] = sg * s;
    }
    if (tid < OUTC) {
        float sg = sbn_g[tid] * rsqrtf(sbn_v[tid] + 1e-5f);
        g_sb[tid] = sbn_b[tid] - sbn_m[tid] * sg;
        float tg = tbn_g[tid] * rsqrtf(tbn_v[tid] + 1e-5f);
        g_tg[tid] = tg;
        g_tb[tid] = tbn_b[tid] - tbn_m[tid] * tg;
    }

    if (tid < 81) {
        int i = tid / 9, j = tid - i * 9;
        Mt[tid] = 0.5f * (adj_after[i * 9 + j] + adj_after[j * 9 + i]);
    }
    __syncthreads();
    if (tid < 9) {
        float s = 0.f;
        for (int j = 0; j < 9; j++) s += Mt[tid * 9 + j];
        d9[tid] = rsqrtf(s);
    }
    __syncthreads();
    if (tid < 81) {
        int i = tid / 9, j = tid - i * 9;
        At[tid] = Mt[tid] * d9[i] * d9[j];
        out[1508 + tid] = At[tid];
    }
    __syncthreads();
    if (tid < 81) {
        int i = tid / 9, j = tid - i * 9;
        float s = 0.f;
        for (int k = 0; k < 9; k++) s += At[i * 9 + k] * At[k * 9 + j];
        At2[tid] = s;
    }
    __syncthreads();
    for (int idx = tid; idx < NCLS * OUTC * WIN; idx += 256) {
        int n = idx / (OUTC * WIN);
        int rem = idx - n * OUTC * WIN;
        int o = rem / WIN, w = rem - o * WIN;
        float s = 0.f;
        for (int wp = 0; wp < 9; wp++) s += fc_a_w[n * 576 + o * 9 + wp] * At2[wp * 9 + w];
        g_fcA[idx] = s;
    }
    __syncthreads();

    if (tid < 81) {
        int i = tid / 9, j = tid - i * 9;
        Mt[tid] = 0.5f * (adj_before[i * 9 + j] + adj_before[j * 9 + i]);
    }
    __syncthreads();
    if (tid < 9) {
        float s = 0.f;
        for (int j = 0; j < 9; j++) s += Mt[tid * 9 + j];
        d9[tid] = rsqrtf(s);
    }
    __syncthreads();
    if (tid < 81) {
        int i = tid / 9, j = tid - i * 9;
        At[tid] = Mt[tid] * d9[i] * d9[j];
        out[1589 + tid] = At[tid];
    }
    __syncthreads();
    if (tid < 81) {
        int i = tid / 9, j = tid - i * 9;
        float s = 0.f;
        for (int k = 0; k < 9; k++) s += At[i * 9 + k] * At[k * 9 + j];
        g_Atb2[tid] = s;
    }
}

// ============================================================
// fold W1 into tconv -> g_w2[c][k][o]
// ============================================================
__global__ void k_wt2(const float* __restrict__ tconv_w) {
    int idx = blockIdx.x * 256 + threadIdx.x;
    if (idx < CIN * KS * OUTC) {
        int c = idx / (KS * OUTC);
        int r = idx - c * (KS * OUTC);
        int k = r / OUTC, o = r - k * OUTC;
        float s = 0.f;
        #pragma unroll 8
        for (int i = 0; i < OUTC; i++)
            s += tconv_w[(o * OUTC + i) * KS + k] * g_W1[i * CIN + c];
        g_w2[idx] = s;
    }
}

// ============================================================
// g_w3: bf16x2 weights in m16n8k16 B-fragment layout
// idx = c*2048 + chunk*512 + ntg*64 + lane*2 + r  (all b32)
// lane: g=lane>>2, tig=lane&3; o = ntg*8+g; k0 = chunk*16 + 2*tig + 8*r
// value = pack_bf(w2[c][k0][o], w2[c][k0+1][o]) with zero pad at k>=63
// ============================================================
__global__ void k_wt3() {
    int idx = blockIdx.x * 256 + threadIdx.x;
    if (idx < CIN * 2048) {
        int c = idx >> 11;
        int rem = idx & 2047;
        int chunk = rem >> 9;
        int ntg = (rem >> 6) & 7;
        int lane = (rem >> 1) & 31;
        int r = rem & 1;
        int g = lane >> 2, tig = lane & 3;
        int o = ntg * 8 + g;
        int k0 = chunk * 16 + 2 * tig + 8 * r;
        float v0 = (k0 < KS) ? g_w2[(c * KS + k0) * OUTC + o] : 0.f;
        float v1 = (k0 + 1 < KS) ? g_w2[(c * KS + k0 + 1) * OUTC + o] : 0.f;
        ((uint32_t*)g_w3)[idx] = pack_bf(v0, v1);
    }
}

// ============================================================
// bias fold, parallel: q[o][k] = sum_i w[o][i][k]*sb[i]
// ============================================================
__global__ void k_biasq(const float* __restrict__ tconv_w) {
    int idx = blockIdx.x * 256 + threadIdx.x;     // o*KS + k
    if (idx < OUTC * KS) {
        int o = idx / KS, k = idx - o * KS;
        const float* wp = tconv_w + o * OUTC * KS + k;
        float s = 0.f;
        #pragma unroll 8
        for (int i = 0; i < OUTC; i++)
            s += wp[i * KS] * g_sb[i];
        g_q[idx] = s;
    }
}

// cumsum per o (tiny, L2-hot)
__global__ void k_bias2() {
    int o = threadIdx.x;
    if (o >= OUTC) return;
    float cum = 0.f;
    g_C[o * (KS + 1)] = 0.f;
    for (int k = 0; k < KS; k++) {
        cum += g_q[o * KS + k];
        g_C[o * (KS + 1) + k + 1] = cum;
    }
}

// ============================================================
// branch-B time mix (view regrouping)
// ============================================================
__global__ void k_xb(const float* __restrict__ x) {
    const int bk = blockIdx.x;
    const int b = bk / CIN, r = bk - b * CIN;
    const int s = threadIdx.x;
    if (s >= SEG) return;
    float v[WIN];
    #pragma unroll
    for (int pp = 0; pp < WIN; pp++) {
        int m = 22 * pp + r;
        int c = m / 9, w = m - c * 9;
        v[pp] = x[((size_t)b * CIN + c) * TLEN + w * SEG + s];
    }
    float* dst = g_xb + ((size_t)b * CIN + r) * TLEN + s;
    #pragma unroll
    for (int p = 0; p < WIN; p++) {
        float a = 0.f;
        #pragma unroll
        for (int pp = 0; pp < WIN; pp++)
            a = fmaf(g_Atb2[p * 9 + pp], v[pp], a);
        dst[p * SEG] = a;
    }
}

// ============================================================
// temporal mean
// ============================================================
__global__ void k_mean(const float* __restrict__ x) {
    __shared__ float red[4];
    const int rc = blockIdx.x;
    const float* src = x + (size_t)rc * TLEN;
    float psum = 0.f;
    for (int idx = threadIdx.x; idx < TLEN; idx += 128) psum += src[idx];
    for (int m = 16; m >= 1; m >>= 1) psum += __shfl_xor_sync(0xffffffffu, psum, m);
    if ((threadIdx.x & 31) == 0) red[threadIdx.x >> 5] = psum;
    __syncthreads();
    if (threadIdx.x == 0)
        g_xmean[rc] = (red[0] + red[1] + red[2] + red[3]) * (1.f / (float)TLEN);
}

// ============================================================
// MAIN: bf16 m16n8k16 mma.sync conv + bias + BN + GELU + seg-pool
// grid (9, 512), 128 threads. Warp (wm, wn): 64 t x 32 o.
// y stored as overlapping bf16x2 pairs: yp[i] = (y[i], y[i+1]).
// Toeplitz identity: a1 (row g+8, col 2tig) == a2 (row g, col 2tig+8).
// ============================================================
#define DYN_SMEM ((4224 + 4096 + 128) * 4)   // y pairs + 2x weight buf (=C table) + s_part

__global__ void __launch_bounds__(128) k_conv5(const float* __restrict__ x) {
    extern __shared__ float sm[];
    float* y_s = sm;                  // [22][192] bf16x2 pairs
    float* w_s = sm + 4224;           // [2][2048] b32 fragments; reused as C table [64][64]
    float* s_part = sm + 4224 + 4096; // [2][64]
    __shared__ float s_q[64], s_tg[64], s_tb[64];

    const int w = blockIdx.x;
    const int bb = blockIdx.y;
    const int tid = threadIdx.x;
    const int wid = tid >> 5, lane = tid & 31;
    const int wm = wid & 1, wn = wid >> 1;
    const int g = lane >> 2, tig = lane & 3;
    const int t0 = w * SEG - 31;
    const float* src = ((bb >> 8) ? g_xb : x) + (size_t)(bb & 255) * CIN * TLEN;

    // y halo tile as overlapping bf16x2 pairs (187 valid positions, rest zero)
    uint32_t* yu = (uint32_t*)y_s;
    for (int idx = tid; idx < CIN * 192; idx += 128) {
        int c = idx / 192, tt = idx - c * 192;
        int gt = t0 + tt;
        float v0 = (gt >= 0 && gt < TLEN && tt < 187) ? src[(size_t)c * TLEN + gt] : 0.f;
        float v1 = (gt + 1 >= 0 && gt + 1 < TLEN && tt + 1 < 187) ? src[(size_t)c * TLEN + gt + 1] : 0.f;
        yu[idx] = pack_bf(v0, v1);
    }
    // first channel's weights
    {
        const float4* s4 = (const float4*)g_w3;
        float4* d4 = (float4*)w_s;
        #pragma unroll
        for (int j = 0; j < 4; j++) d4[j * 128 + tid] = s4[j * 128 + tid];
    }
    if (tid < 64) { s_q[tid] = g_C[tid * 64 + 63]; s_tg[tid] = g_tg[tid]; s_tb[tid] = g_tb[tid]; }
    __syncthreads();

    float acc[4][4][4];
    #pragma unroll
    for (int m = 0; m < 4; m++)
        #pragma unroll
        for (int nt = 0; nt < 4; nt++)
            #pragma unroll
            for (int j = 0; j < 4; j++) acc[m][nt][j] = 0.f;

    for (int c = 0; c < CIN; c++) {
        float4 pf[4];
        if (c < CIN - 1) {
            const float4* s4 = (const float4*)(g_w3 + (c + 1) * 2048);
            #pragma unroll
            for (int j = 0; j < 4; j++) pf[j] = s4[j * 128 + tid];
        }
        const uint32_t* ya = yu + c * 192 + wm * 64 + g + 2 * tig;
        const uint32_t* wb = (const uint32_t*)w_s + (c & 1) * 2048 + wn * 256 + lane * 2;

        #pragma unroll
        for (int chunk = 0; chunk < 4; chunk++) {
            uint32_t a[4][4];
            #pragma unroll
            for (int m = 0; m < 4; m++) {
                const uint32_t* p = ya + m * 16 + chunk * 16;
                uint32_t p0 = p[0], p1 = p[8], p2 = p[16];
                a[m][0] = p0; a[m][1] = p1; a[m][2] = p1; a[m][3] = p2;
            }
            #pragma unroll
            for (int nt = 0; nt < 4; nt++) {
                uint2 bv = *(const uint2*)(wb + chunk * 512 + nt * 64);
                #pragma unroll
                for (int m = 0; m < 4; m++)
                    mma16(acc[m][nt], a[m], bv.x, bv.y);
            }
        }
        __syncthreads();
        if (c < CIN - 1) {
            float4* d4 = (float4*)(w_s + ((c + 1) & 1) * 2048);
            #pragma unroll
            for (int j = 0; j < 4; j++) d4[j * 128 + tid] = pf[j];
            __syncthreads();
        }
    }

    // ---- epilogue ----
    const bool edge = (w == 0) || (w == WIN - 1);
    if (edge) {
        for (int j = tid; j < 4096; j += 128) w_s[j] = g_C[j];
    }
    __syncthreads();

    const int tg_base = w * SEG;
    #pragma unroll
    for (int nt = 0; nt < 4; nt++) {
        int o0 = wn * 32 + nt * 8 + 2 * tig, o1 = o0 + 1;
        float tg0 = s_tg[o0], tb0_ = s_tb[o0], tg1 = s_tg[o1], tb1_ = s_tb[o1];
        float q0 = s_q[o0], q1 = s_q[o1];
        float s0 = 0.f, s1 = 0.f;
        #pragma unroll
        for (int m = 0; m < 4; m++) {
            int t_a = wm * 64 + m * 16 + g;
            int t_b = t_a + 8;
            float b0a = q0, b1a = q1, b0b = q0, b1b = q1;
            if (edge) {
                int tag = tg_base + t_a;
                int kmin = 31 - tag; kmin = kmin < 0 ? 0 : kmin;
                int kx = 1156 - tag; kx = kx > 63 ? 63 : kx;
                b0a = w_s[o0 * 64 + kx] - w_s[o0 * 64 + kmin];
                b1a = w_s[o1 * 64 + kx] - w_s[o1 * 64 + kmin];
                int tbg = tag + 8;
                int kminb = 31 - tbg; kminb = kminb < 0 ? 0 : kminb;
                int kxb = 1156 - tbg; kxb = kxb > 63 ? 63 : kxb;
                b0b = w_s[o0 * 64 + kxb] - w_s[o0 * 64 + kminb];
                b1b = w_s[o1 * 64 + kxb] - w_s[o1 * 64 + kminb];
            }
            if (t_a < SEG) {
                s0 += gelu_exact(fmaf(acc[m][nt][0] + b0a, tg0, tb0_));
                s1 += gelu_exact(fmaf(acc[m][nt][1] + b1a, tg1, tb1_));
            }
            if (t_b < SEG) {
                s0 += gelu_exact(fmaf(acc[m][nt][2] + b0b, tg0, tb0_));
                s1 += gelu_exact(fmaf(acc[m][nt][3] + b1b, tg1, tb1_));
            }
        }
        s0 += __shfl_xor_sync(0xffffffffu, s0, 4);
        s0 += __shfl_xor_sync(0xffffffffu, s0, 8);
        s0 += __shfl_xor_sync(0xffffffffu, s0, 16);
        s1 += __shfl_xor_sync(0xffffffffu, s1, 4);
        s1 += __shfl_xor_sync(0xffffffffu, s1, 8);
        s1 += __shfl_xor_sync(0xffffffffu, s1, 16);
        if (g == 0) {
            s_part[wm * 64 + o0] = s0;
            s_part[wm * 64 + o1] = s1;
        }
    }
    __syncthreads();
    if (tid < 64)
        g_pool[(tid * 9 + w) * (2 * BATCH) + bb] = (s_part[tid] + s_part[64 + tid]) * 0.008f;
}

// ============================================================
// final FCs + fuse (pool now transposed -> coalesced loads)
// ============================================================
__global__ void k_fc(const float* __restrict__ fc_a_b,
                     const float* __restrict__ fc_b_w, const float* __restrict__ fc_b_b,
                     const float* __restrict__ fc_c_w, const float* __restrict__ fc_c_b,
                     const float* __restrict__ fuse_w, const float* __restrict__ fuse_b,
                     float* __restrict__ out)
{
    __shared__ float sA[NCLS * 576];
    __shared__ float sB[NCLS * 576];
    const int tid = threadIdx.x;
    for (int idx = tid; idx < NCLS * 576; idx += 256) {
        sA[idx] = g_fcA[idx];
        sB[idx] = fc_b_w[idx];
    }
    __syncthreads();
    const int b = tid;
    float la[4], lb[4], lc[4];
    #pragma unroll
    for (int n = 0; n < 4; n++) { la[n] = fc_a_b[n]; lb[n] = fc_b_b[n]; lc[n] = fc_c_b[n]; }
    for (int j = 0; j < 576; j++) {
        float va = g_pool[j * (2 * BATCH) + b];
        float vb = g_pool[j * (2 * BATCH) + BATCH + b];
        #pragma unroll
        for (int n = 0; n < 4; n++) {
            la[n] = fmaf(sA[n * 576 + j], va, la[n]);
            lb[n] = fmaf(sB[n * 576 + j], vb, lb[n]);
        }
    }
    for (int c = 0; c < CIN; c++) {
        float v = g_xmean[b * CIN + c];
        #pragma unroll
        for (int n = 0; n < 4; n++) lc[n] = fmaf(fc_c_w[n * CIN + c], v, lc[n]);
    }
    #pragma unroll
    for (int n = 0; n < 4; n++) {
        float o = fuse_b[n];
        #pragma unroll
        for (int m = 0; m < 4; m++) {
            o = fmaf(fuse_w[n * 12 + m], la[m], o);
            o = fmaf(fuse_w[n * 12 + 4 + m], lb[m], o);
            o = fmaf(fuse_w[n * 12 + 8 + m], lc[m], o);
        }
        out[b * 4 + n] = o;
    }
}

// ============================================================
// launch
// ============================================================
extern "C" void kernel_launch(void* const* d_in, const int* in_sizes, int n_in,
                              void* d_out, int out_size) {
    const float* x        = (const float*)d_in[0];
    const float* edge_w   = (const float*)d_in[1];
    const float* sconv_w  = (const float*)d_in[2];
    const float* sbn_g    = (const float*)d_in[3];
    const float* sbn_b    = (const float*)d_in[4];
    const float* sbn_m    = (const float*)d_in[5];
    const float* sbn_v    = (const float*)d_in[6];
    const float* tconv_w  = (const float*)d_in[7];
    const float* tbn_g    = (const float*)d_in[8];
    const float* tbn_b    = (const float*)d_in[9];
    const float* tbn_m    = (const float*)d_in[10];
    const float* tbn_v    = (const float*)d_in[11];
    const float* adj_a    = (const float*)d_in[12];
    const float* adj_b    = (const float*)d_in[13];
    const float* fc_a_w   = (const float*)d_in[14];
    const float* fc_a_b   = (const float*)d_in[15];
    const float* fc_b_w   = (const float*)d_in[16];
    const float* fc_b_b   = (const float*)d_in[17];
    const float* fc_c_w   = (const float*)d_in[18];
    const float* fc_c_b   = (const float*)d_in[19];
    const float* fuse_w   = (const float*)d_in[20];
    const float* fuse_b   = (const float*)d_in[21];
    float* out = (float*)d_out;

    cudaFuncSetAttribute(k_conv5, cudaFuncAttributeMaxDynamicSharedMemorySize, DYN_SMEM);

    k_prep<<<1, 256>>>(edge_w, sconv_w, sbn_g, sbn_b, sbn_m, sbn_v,
                       tbn_g, tbn_b, tbn_m, tbn_v, adj_a, adj_b, fc_a_w, out);
    k_wt2<<<(CIN * KS * OUTC + 255) / 256, 256>>>(tconv_w);
    k_wt3<<<(CIN * 2048 + 255) / 256, 256>>>();
    k_biasq<<<(OUTC * KS + 255) / 256, 256>>>(tconv_w);
    k_bias2<<<1, 64>>>();
    k_xb<<<BATCH * CIN, 128>>>(x);
    k_mean<<<BATCH * CIN, 128>>>(x);
    k_conv5<<<dim3(WIN, 2 * BATCH), 128, DYN_SMEM>>>(x);
    k_fc<<<1, 256>>>(fc_a_b, fc_b_w, fc_b_b, fc_c_w, fc_c_b, fuse_w, fuse_b, out);
}